// round 15
// baseline (speedup 1.0000x reference)
#include <cuda_runtime.h>
#include <math.h>

#define Bn 16
#define Cn 64
#define Hn 256
#define HWn 65536

__device__ float g_x[Bn*Cn*HWn];       // activations [b][c][h][w] (in place)
__device__ float g_G[Bn*Cn*Hn*32];     // fwd w-DFT: [bc*256+h][kx](re,im)
__device__ float g_F[512*2048];        // fwd spectrum, mode-major: [mode][re|im][bc]
__device__ float g_F2[Bn*Cn*1024];     // after spectral mix [bo][mode][2]
__device__ float g_Gi[Bn*Cn*8192];     // inv h-DFT [bo][kx][h](re,im) interleaved
__device__ float g_part[Bn*Cn*128];    // proj partial sums per (b,o,hb)
__device__ float g_ct[256];
__device__ float g_st[256];
__device__ float2 g_cc2[256];
__device__ float2 g_ss2[256];
__device__ float g_Wtr[4*512*4096];    // transposed weights: [l][mode][i*64+o]
__device__ float g_Wti[4*512*4096];

__device__ __forceinline__ float gelu(float x) {
    return 0.5f * x * (1.0f + erff(x * 0.70710678f));
}

__device__ __forceinline__ float2 ffma2(float2 a, float2 b, float2 c) {
    float2 d;
    asm("fma.rn.f32x2 %0, %1, %2, %3;"
        : "=l"(*(unsigned long long*)&d)
        : "l"(*(unsigned long long*)&a),
          "l"(*(unsigned long long*)&b),
          "l"(*(unsigned long long*)&c));
    return d;
}

// ---------------- compile-time twiddles (forced constant-fold) ----------------
constexpr double TPI_ = 3.141592653589793238462643383279502884;
constexpr double tcos_(double x) {
    double t = 1.0, s = 1.0;
    for (int i = 1; i <= 16; i++) { t = -t * x * x / ((2.0 * i - 1.0) * (2.0 * i)); s += t; }
    return s;
}
constexpr double tsin_(double x) {
    double t = x, s = x;
    for (int i = 1; i <= 16; i++) { t = -t * x * x / ((2.0 * i) * (2.0 * i + 1.0)); s += t; }
    return s;
}
constexpr double ang_(int n) { return ((n <= 128) ? n : n - 256) * (TPI_ / 128.0); }
template<int N> struct TwN {
    static constexpr float C = (float)tcos_(ang_(N));      // cos(2pi N/256)
    static constexpr float S = (float)(-tsin_(ang_(N)));   // -sin(2pi N/256)
};

// unfolded: acc[k] += x * e^{-2pi i (W*k)/256}
template<int W, int K> struct KL {
    static __device__ __forceinline__ void run(float x, float2* a) {
        constexpr int N = (W * K) & 255;
        a[K].x = fmaf(x, TwN<N>::C, a[K].x);
        a[K].y = fmaf(x, TwN<N>::S, a[K].y);
        KL<W, K + 1>::run(x, a);
    }
};
template<int W> struct KL<W, 16> {
    static __device__ __forceinline__ void run(float, float2*) {}
};
// folded pair (w, 256-w): Re += u*cos, Im += v*(-sin)
template<int W, int K> struct KLF {
    static __device__ __forceinline__ void run(float u, float v, float2* a) {
        constexpr int N = (W * K) & 255;
        a[K].x = fmaf(u, TwN<N>::C, a[K].x);
        a[K].y = fmaf(v, TwN<N>::S, a[K].y);
        KLF<W, K + 1>::run(u, v, a);
    }
};
template<int W> struct KLF<W, 16> {
    static __device__ __forceinline__ void run(float, float, float2*) {}
};
template<int C, int J> struct JF {
    static __device__ __forceinline__ void run(const float* xr, float2* a) {
        float lo = xr[J];
        float hi = xr[34 + 32 - J];
        KLF<32 * C + J, 0>::run(lo + hi, lo - hi, a);
        JF<C, J + 1>::run(xr, a);
    }
};
template<int C> struct JF<C, 32> {
    static __device__ __forceinline__ void run(const float*, float2*) {}
};

template<int CC>
__device__ __forceinline__ void fw_pair(int tid, int r0, float* xs, float2* acc) {
    __syncthreads();
    #pragma unroll 2
    for (int i = tid; i < 2048; i += 256) {
        int r = i >> 3, jq = (i & 7) * 4;
        float4 v = *(const float4*)&g_x[(r0 + r) * 256 + CC * 32 + jq];
        float4 w = *(const float4*)&g_x[(r0 + r) * 256 + (7 - CC) * 32 + jq];
        float* p = xs + r * 67 + jq;
        p[0] = v.x; p[1] = v.y; p[2] = v.z; p[3] = v.w;
        float* q = p + 34;
        q[0] = w.x; q[1] = w.y; q[2] = w.z; q[3] = w.w;
    }
    __syncthreads();
    const float* xr = xs + tid * 67;
    KL<CC * 32, 0>::run(xr[0], acc);
    KL<(7 - CC) * 32, 0>::run(xr[34], acc);
    JF<CC, 1>::run(xr, acc);
}

// ---------------- fwd w-DFT (R10 structure, stride 67) ----------------
__global__ void __launch_bounds__(256) k_fwd_w_imm() {
    extern __shared__ float xs[];              // 256*67 floats
    int tid = threadIdx.x, r0 = blockIdx.x * 256;
    float2 acc[16];
    #pragma unroll
    for (int k = 0; k < 16; k++) acc[k] = make_float2(0.f, 0.f);
    fw_pair<0>(tid, r0, xs, acc);
    fw_pair<1>(tid, r0, xs, acc);
    fw_pair<2>(tid, r0, xs, acc);
    fw_pair<3>(tid, r0, xs, acc);
    float* gp = g_G + (r0 + tid) * 32;
    #pragma unroll
    for (int k = 0; k < 8; k++) {
        float4 v = make_float4(acc[2 * k].x, acc[2 * k].y, acc[2 * k + 1].x, acc[2 * k + 1].y);
        *(float4*)&gp[4 * k] = v;
    }
}

// ---------------- init ----------------
__global__ void k_init() {
    int tid = threadIdx.x;
    double s, c;
    sincospi((double)tid / 128.0, &s, &c);
    g_ct[tid] = (float)c;  g_st[tid] = (float)s;
    g_cc2[tid] = make_float2((float)c, (float)c);
    g_ss2[tid] = make_float2((float)s, (float)s);
}

// ---------------- one-time weight transpose ----------------
__global__ void __launch_bounds__(256) k_wprep(const float* __restrict__ w1r, const float* __restrict__ w1i,
                                               const float* __restrict__ w2r, const float* __restrict__ w2i) {
    __shared__ float tile[32][257];
    int bx = blockIdx.x;
    int l = bx & 3, src = (bx >> 2) & 3, io0 = (bx >> 4) * 32;
    const float* sp;
    if      (src == 0) sp = w1r;
    else if (src == 1) sp = w1i;
    else if (src == 2) sp = w2r;
    else               sp = w2i;
    sp += (long)l * 1048576 + (long)io0 * 256;
    int t = threadIdx.x;
    #pragma unroll 4
    for (int io = 0; io < 32; io++) tile[io][t] = sp[io * 256 + t];
    __syncthreads();
    float* tp = ((src & 1) ? g_Wti : g_Wtr) + (long)l * 2097152 + ((src >= 2) ? (long)256 * 4096 : 0) + io0;
    int lane = t & 31, row = t >> 5;
    #pragma unroll 4
    for (int j = 0; j < 32; j++) {
        int m = row + j * 8;
        tp[(long)m * 4096 + lane] = tile[lane][m];
    }
}

// ---------------- lift: o-pair packed ----------------
__global__ void __launch_bounds__(256) k_lift(const float* __restrict__ grid,
                                              const float* __restrict__ lw,
                                              const float* __restrict__ lb) {
    __shared__ float2 wt[480];   // [c][op]
    __shared__ float2 bs2[32];
    int tid = threadIdx.x;
    for (int i = tid; i < 480; i += 256) {
        int c = i >> 5, op = i & 31;
        wt[i] = make_float2(lw[(op * 2) * 15 + c], lw[(op * 2 + 1) * 15 + c]);
    }
    if (tid < 32) bs2[tid] = make_float2(lb[2 * tid], lb[2 * tid + 1]);
    __syncthreads();
    int p = blockIdx.x * 256 + tid;
    int b = p >> 16, hw = p & 65535;
    float2 xx[15];
    const float* gp = grid + b * 15 * HWn + hw;
    #pragma unroll
    for (int c = 0; c < 15; c++) { float x = gp[c * HWn]; xx[c] = make_float2(x, x); }
    float* xp = g_x + b * Cn * HWn + hw;
    #pragma unroll 2
    for (int op = 0; op < 32; op++) {
        float2 a = bs2[op];
        #pragma unroll
        for (int c = 0; c < 15; c++) a = ffma2(xx[c], wt[c * 32 + op], a);
        xp[(2 * op) * HWn]     = gelu(a.x);
        xp[(2 * op + 1) * HWn] = gelu(a.y);
    }
}

// ---------------- fwd h-DFT: conjugate-pair folded (R10) ----------------
__global__ void __launch_bounds__(272) k_fwd_h() {
    __shared__ float Gs[8192];
    __shared__ float2 scc[256], sss[256];
    int tid = threadIdx.x, bc = blockIdx.x;
    const float* gp = g_G + bc * 8192;
    for (int i = tid; i < 8192; i += 272) Gs[i] = gp[i];
    for (int i = tid; i < 256; i += 272) { scc[i] = g_cc2[i]; sss[i] = g_ss2[i]; }
    __syncthreads();
    int sp = tid >> 4, kx = tid & 15;
    int kyv = (sp == 16) ? 240 : sp;
    float2 P = make_float2(0.f, 0.f), Q = make_float2(0.f, 0.f);
    int idx = 0;
    #pragma unroll 4
    for (int h = 0; h < 256; h++) {
        float2 g = *(const float2*)&Gs[h * 32 + kx * 2];
        P = ffma2(g, scc[idx], P);
        Q = ffma2(g, sss[idx], Q);
        idx = (idx + kyv) & 255;
    }
    int m = sp * 16 + kx;
    g_F[m * 2048 + bc]        = P.x + Q.y;
    g_F[m * 2048 + 1024 + bc] = P.y - Q.x;
    if (sp >= 1 && sp <= 15) {
        int m2 = (32 - sp) * 16 + kx;
        g_F[m2 * 2048 + bc]        = P.x - Q.y;
        g_F[m2 * 2048 + 1024 + bc] = P.y + Q.x;
    }
}

// ---------------- spectral multiply (R8) ----------------
__global__ void __launch_bounds__(256) k_spec(int l) {
    __shared__ float Wr[4096], Wi[4096], Ar[1024], Ai[1024];
    int m = blockIdx.x, t = threadIdx.x;
    const float* wr = g_Wtr + (long)l * 2097152 + (long)m * 4096;
    const float* wi = g_Wti + (long)l * 2097152 + (long)m * 4096;
    for (int i = t; i < 4096; i += 256) { Wr[i] = wr[i]; Wi[i] = wi[i]; }
    const float* fp = g_F + (long)m * 2048;
    for (int i = t; i < 1024; i += 256) { Ar[i] = fp[i]; Ai[i] = fp[1024 + i]; }
    __syncthreads();
    int o = t & 63, bq = t >> 6;
    float orr[4], oii[4];
    #pragma unroll
    for (int u = 0; u < 4; u++) { orr[u] = 0.f; oii[u] = 0.f; }
    for (int i = 0; i < 64; i++) {
        float wrv = Wr[i * 64 + o], wiv = Wi[i * 64 + o];
        #pragma unroll
        for (int u = 0; u < 4; u++) {
            float arv = Ar[(bq * 4 + u) * 64 + i], aiv = Ai[(bq * 4 + u) * 64 + i];
            orr[u] = fmaf(arv, wrv, fmaf(-aiv, wiv, orr[u]));
            oii[u] = fmaf(arv, wiv, fmaf( aiv, wrv, oii[u]));
        }
    }
    #pragma unroll
    for (int u = 0; u < 4; u++) {
        int b = bq * 4 + u;
        *(float2*)&g_F2[(b * 64 + o) * 1024 + m * 2] = make_float2(orr[u], oii[u]);
    }
}

// ---------------- inv h-DFT (R8) ----------------
__global__ void __launch_bounds__(256) k_inv_h() {
    __shared__ float Fs[1024];
    __shared__ float2 scc[256], sss[256];
    int tid = threadIdx.x, bo = blockIdx.x;
    const float* fp = g_F2 + bo * 1024;
    for (int i = tid; i < 1024; i += 256) Fs[i] = fp[i];
    scc[tid] = g_cc2[tid]; sss[tid] = g_ss2[tid];
    __syncthreads();
    int h = tid;
    float2 P[16], Q[16];
    #pragma unroll
    for (int k = 0; k < 16; k++) { P[k] = make_float2(0.f, 0.f); Q[k] = make_float2(0.f, 0.f); }
    #pragma unroll 2
    for (int s = 0; s < 32; s++) {
        int ky = (s < 16) ? s : s + 224;
        int idx = (ky * h) & 255;
        float2 cc = scc[idx], ss = sss[idx];
        #pragma unroll
        for (int q = 0; q < 8; q++) {
            float4 f4 = *(const float4*)&Fs[s * 32 + q * 4];
            float2 fa = make_float2(f4.x, f4.y), fb = make_float2(f4.z, f4.w);
            P[2 * q]     = ffma2(fa, cc, P[2 * q]);     Q[2 * q]     = ffma2(fa, ss, Q[2 * q]);
            P[2 * q + 1] = ffma2(fb, cc, P[2 * q + 1]); Q[2 * q + 1] = ffma2(fb, ss, Q[2 * q + 1]);
        }
    }
    float2* go = (float2*)g_Gi + bo * 4096 + h;
    #pragma unroll
    for (int k = 0; k < 16; k++) {
        float sc = (k == 0 ? 1.f : 2.f) * (1.f / 65536.f);
        go[k * 256] = make_float2((P[k].x - Q[k].y) * sc, (P[k].y + Q[k].x) * sc);
    }
}

// ---------------- fused inv w-DFT + skip conv + BN + gelu + residual ----------------
// R12 compute core; fills reorganized: float4 xs fill, conflict-free swt/gis STS.
__global__ void __launch_bounds__(256, 2) k_fuse(const float* __restrict__ skw, const float* __restrict__ skb,
                                                 const float* __restrict__ bng, const float* __restrict__ bnb,
                                                 const float* __restrict__ bnm, const float* __restrict__ bnv,
                                                 int l) {
    extern __shared__ float sm[];
    float* xs   = sm;              // 16896 = 64*264
    float* swt  = xs + 16896;      // 4096: [c][o]
    float* gis  = swt + 4096;      // 2048: [kx][ri][o], ri=1 negated
    float* ctb  = gis + 2048;      // 256
    float* stb  = ctb + 256;       // 256
    float* bnA  = stb + 256;       // 64
    float* bnB  = bnA + 64;        // 64
    float* sbbv = bnB + 64;        // 64
    int tid = threadIdx.x;
    int b = blockIdx.x >> 8, h = blockIdx.x & 255;
    float* xp = g_x + b * 64 * HWn + h * 256;
    // xs fill: float4 both sides, conflict-free STS.128
    #pragma unroll 4
    for (int i = tid; i < 4096; i += 256) {
        int c = i >> 6, w4 = (i & 63) * 4;
        float4 v = *(const float4*)&xp[c * HWn + w4];
        *(float4*)&xs[c * 264 + w4] = v;
    }
    // swt fill: consecutive threads -> consecutive o (conflict-free STS); scattered LDG from L2-hot 16KB
    #pragma unroll 4
    for (int i = tid; i < 4096; i += 256) {
        int o = i & 63, c = i >> 6;
        swt[c * 64 + o] = skw[l * 4096 + o * 64 + c];
    }
    // gis fill: consecutive threads -> consecutive o (conflict-free STS)
    #pragma unroll
    for (int i = tid; i < 1024; i += 256) {
        int o = i & 63, kx = i >> 6;
        float2 v = ((const float2*)g_Gi)[(b * 64 + o) * 4096 + kx * 256 + h];
        gis[kx * 128 + o]      = v.x;
        gis[kx * 128 + 64 + o] = -v.y;
    }
    ctb[tid] = g_ct[tid];  stb[tid] = g_st[tid];
    if (tid < 64) {
        float A = bng[l * 64 + tid] * rsqrtf(bnv[l * 64 + tid] + 1e-5f);
        bnA[tid] = A;
        bnB[tid] = fmaf(-bnm[l * 64 + tid], A, bnb[l * 64 + tid]);
        sbbv[tid] = skb[l * 64 + tid];
    }
    __syncthreads();
    int wb = (tid & 63) * 4, ob = (tid >> 6) * 16;
    float2 acc[8][4];
    #pragma unroll
    for (int ip = 0; ip < 8; ip++) {
        float2 bias = *(const float2*)&sbbv[ob + ip * 2];
        acc[ip][0] = bias; acc[ip][1] = bias; acc[ip][2] = bias; acc[ip][3] = bias;
    }
    for (int c = 0; c < 64; c++) {
        float4 xv = *(const float4*)&xs[c * 264 + wb];
        float2 x0 = make_float2(xv.x, xv.x), x1 = make_float2(xv.y, xv.y);
        float2 x2 = make_float2(xv.z, xv.z), x3 = make_float2(xv.w, xv.w);
        #pragma unroll
        for (int ip = 0; ip < 8; ip++) {
            float2 wv = *(const float2*)&swt[c * 64 + ob + ip * 2];
            acc[ip][0] = ffma2(x0, wv, acc[ip][0]);
            acc[ip][1] = ffma2(x1, wv, acc[ip][1]);
            acc[ip][2] = ffma2(x2, wv, acc[ip][2]);
            acc[ip][3] = ffma2(x3, wv, acc[ip][3]);
        }
    }
    float dc[4], ds[4], tc_[4], ts_[4];
    #pragma unroll
    for (int j = 0; j < 4; j++) {
        dc[j] = ctb[wb + j];  ds[j] = stb[wb + j];
        tc_[j] = 1.f;  ts_[j] = 0.f;
    }
    #pragma unroll 4
    for (int kx = 0; kx < 16; kx++) {
        float2 cc0 = make_float2(tc_[0], tc_[0]), ss0 = make_float2(ts_[0], ts_[0]);
        float2 cc1 = make_float2(tc_[1], tc_[1]), ss1 = make_float2(ts_[1], ts_[1]);
        float2 cc2 = make_float2(tc_[2], tc_[2]), ss2 = make_float2(ts_[2], ts_[2]);
        float2 cc3 = make_float2(tc_[3], tc_[3]), ss3 = make_float2(ts_[3], ts_[3]);
        #pragma unroll
        for (int ip = 0; ip < 8; ip++) {
            float2 gr = *(const float2*)&gis[kx * 128 + ob + ip * 2];
            float2 gi = *(const float2*)&gis[kx * 128 + 64 + ob + ip * 2];
            acc[ip][0] = ffma2(gr, cc0, acc[ip][0]);  acc[ip][0] = ffma2(gi, ss0, acc[ip][0]);
            acc[ip][1] = ffma2(gr, cc1, acc[ip][1]);  acc[ip][1] = ffma2(gi, ss1, acc[ip][1]);
            acc[ip][2] = ffma2(gr, cc2, acc[ip][2]);  acc[ip][2] = ffma2(gi, ss2, acc[ip][2]);
            acc[ip][3] = ffma2(gr, cc3, acc[ip][3]);  acc[ip][3] = ffma2(gi, ss3, acc[ip][3]);
        }
        #pragma unroll
        for (int j = 0; j < 4; j++) {
            float nc = tc_[j] * dc[j] - ts_[j] * ds[j];
            ts_[j] = fmaf(tc_[j], ds[j], ts_[j] * dc[j]);
            tc_[j] = nc;
        }
    }
    #pragma unroll
    for (int ip = 0; ip < 8; ip++) {
        int o0 = ob + ip * 2, o1 = o0 + 1;
        float A0 = bnA[o0], B0 = bnB[o0], A1 = bnA[o1], B1 = bnB[o1];
        float4 r0, r1;
        r0.x = gelu(fmaf(acc[ip][0].x, A0, B0)) + xs[o0 * 264 + wb];
        r0.y = gelu(fmaf(acc[ip][1].x, A0, B0)) + xs[o0 * 264 + wb + 1];
        r0.z = gelu(fmaf(acc[ip][2].x, A0, B0)) + xs[o0 * 264 + wb + 2];
        r0.w = gelu(fmaf(acc[ip][3].x, A0, B0)) + xs[o0 * 264 + wb + 3];
        r1.x = gelu(fmaf(acc[ip][0].y, A1, B1)) + xs[o1 * 264 + wb];
        r1.y = gelu(fmaf(acc[ip][1].y, A1, B1)) + xs[o1 * 264 + wb + 1];
        r1.z = gelu(fmaf(acc[ip][2].y, A1, B1)) + xs[o1 * 264 + wb + 2];
        r1.w = gelu(fmaf(acc[ip][3].y, A1, B1)) + xs[o1 * 264 + wb + 3];
        *(float4*)&xp[o0 * HWn + wb] = r0;
        *(float4*)&xp[o1 * HWn + wb] = r1;
    }
}

// ---------------- proj conv + gelu + partial mean: 2 pixels/thread, o-pair packed ----------------
__global__ void __launch_bounds__(256) k_proj(const float* __restrict__ pw, const float* __restrict__ pb) {
    __shared__ float2 pwt[2048];    // [c][op]
    __shared__ float2 pbs[32];
    __shared__ float wsum[64][8];
    int tid = threadIdx.x;
    int b = blockIdx.x >> 7, hb = blockIdx.x & 127;
    for (int i = tid; i < 2048; i += 256) {
        int c = i >> 5, op = i & 31;
        pwt[i] = make_float2(pw[(op * 2) * 64 + c], pw[(op * 2 + 1) * 64 + c]);
    }
    if (tid < 32) pbs[tid] = make_float2(pb[2 * tid], pb[2 * tid + 1]);
    __syncthreads();
    const float* xp = g_x + (b * 64) * HWn + hb * 512 + tid;
    float xv0[64], xv1[64];
    #pragma unroll
    for (int c = 0; c < 64; c++) { xv0[c] = xp[c * HWn]; xv1[c] = xp[c * HWn + 256]; }
    int lane = tid & 31, wid = tid >> 5;
    #pragma unroll 1
    for (int g = 0; g < 8; g++) {
        float2 a0[4], a1[4];
        #pragma unroll
        for (int j = 0; j < 4; j++) { float2 bi = pbs[g * 4 + j]; a0[j] = bi; a1[j] = bi; }
        #pragma unroll
        for (int c = 0; c < 64; c++) {
            float2 x0 = make_float2(xv0[c], xv0[c]);
            float2 x1 = make_float2(xv1[c], xv1[c]);
            #pragma unroll
            for (int j = 0; j < 4; j++) {
                float2 wv = pwt[c * 32 + g * 4 + j];
                a0[j] = ffma2(x0, wv, a0[j]);
                a1[j] = ffma2(x1, wv, a1[j]);
            }
        }
        #pragma unroll
        for (int j = 0; j < 4; j++) {
            float v0 = gelu(a0[j].x) + gelu(a1[j].x);
            float v1 = gelu(a0[j].y) + gelu(a1[j].y);
            #pragma unroll
            for (int off = 16; off; off >>= 1) {
                v0 += __shfl_down_sync(0xffffffffu, v0, off);
                v1 += __shfl_down_sync(0xffffffffu, v1, off);
            }
            if (lane == 0) {
                wsum[g * 8 + j * 2][wid]     = v0;
                wsum[g * 8 + j * 2 + 1][wid] = v1;
            }
        }
    }
    __syncthreads();
    if (tid < 64) {
        float s = 0.f;
        #pragma unroll
        for (int j = 0; j < 8; j++) s += wsum[tid][j];
        g_part[(b * 64 + tid) * 128 + hb] = s;
    }
}

__global__ void __launch_bounds__(128) k_head(const float* __restrict__ env, const float* __restrict__ d1d,
    const float* __restrict__ dw1, const float* __restrict__ db1,
    const float* __restrict__ dw2, const float* __restrict__ db2,
    const float* __restrict__ dw3, const float* __restrict__ db3,
    const float* __restrict__ iw1, const float* __restrict__ ib1,
    const float* __restrict__ iw2, const float* __restrict__ ib2,
    const float* __restrict__ iw3, const float* __restrict__ ib3,
    float* __restrict__ out) {
    __shared__ float feat[108], h1[128], h2[64];
    int b = blockIdx.x, t = threadIdx.x;
    if (t < 64) {
        float s = 0.f;
        const float* pp = g_part + (b * 64 + t) * 128;
        for (int h = 0; h < 128; h++) s += pp[h];
        feat[t] = s * (1.0f / 65536.0f);
    } else if (t < 104) feat[t] = env[b * 40 + t - 64];
    else if (t < 108)   feat[t] = d1d[b * 4 + t - 104];
    __syncthreads();
    { float a = db1[t];
      for (int k = 0; k < 108; k++) a = fmaf(feat[k], dw1[t * 108 + k], a);
      h1[t] = gelu(a); }
    __syncthreads();
    if (t < 64) { float a = db2[t];
      for (int k = 0; k < 128; k++) a = fmaf(h1[k], dw2[t * 128 + k], a);
      h2[t] = gelu(a); }
    __syncthreads();
    if (t < 8) { float a = db3[t];
      for (int k = 0; k < 64; k++) a = fmaf(h2[k], dw3[t * 64 + k], a);
      out[b * 8 + t] = a; }
    __syncthreads();
    { float a = ib1[t];
      for (int k = 0; k < 108; k++) a = fmaf(feat[k], iw1[t * 108 + k], a);
      h1[t] = gelu(a); }
    __syncthreads();
    if (t < 64) { float a = ib2[t];
      for (int k = 0; k < 128; k++) a = fmaf(h1[k], iw2[t * 128 + k], a);
      h2[t] = gelu(a); }
    __syncthreads();
    if (t < 4) { float a = ib3[t];
      for (int k = 0; k < 64; k++) a = fmaf(h2[k], iw3[t * 64 + k], a);
      out[128 + b * 4 + t] = a; }
}

extern "C" void kernel_launch(void* const* d_in, const int* in_sizes, int n_in,
                              void* d_out, int out_size) {
    const float* grid_in = (const float*)d_in[0];
    const float* env  = (const float*)d_in[1];
    const float* d1d  = (const float*)d_in[2];
    const float* lw   = (const float*)d_in[3];
    const float* lb   = (const float*)d_in[4];
    const float* w1r  = (const float*)d_in[5];
    const float* w1i  = (const float*)d_in[6];
    const float* w2r  = (const float*)d_in[7];
    const float* w2i  = (const float*)d_in[8];
    const float* skw  = (const float*)d_in[9];
    const float* skb  = (const float*)d_in[10];
    const float* bng  = (const float*)d_in[11];
    const float* bnb  = (const float*)d_in[12];
    const float* bnm  = (const float*)d_in[13];
    const float* bnv  = (const float*)d_in[14];
    const float* pw   = (const float*)d_in[15];
    const float* pb   = (const float*)d_in[16];
    const float* dw1  = (const float*)d_in[17];
    const float* db1  = (const float*)d_in[18];
    const float* dw2  = (const float*)d_in[19];
    const float* db2  = (const float*)d_in[20];
    const float* dw3  = (const float*)d_in[21];
    const float* db3  = (const float*)d_in[22];
    const float* iw1  = (const float*)d_in[23];
    const float* ib1  = (const float*)d_in[24];
    const float* iw2  = (const float*)d_in[25];
    const float* ib2  = (const float*)d_in[26];
    const float* iw3  = (const float*)d_in[27];
    const float* ib3  = (const float*)d_in[28];
    float* out = (float*)d_out;

    static bool attr_done = false;
    if (!attr_done) {
        cudaFuncSetAttribute(k_fwd_w_imm, cudaFuncAttributeMaxDynamicSharedMemorySize, 68608);
        cudaFuncSetAttribute(k_fuse, cudaFuncAttributeMaxDynamicSharedMemorySize, 94976);
        attr_done = true;
    }

    k_init<<<1, 256>>>();
    k_wprep<<<2048, 256>>>(w1r, w1i, w2r, w2i);
    k_lift<<<4096, 256>>>(grid_in, lw, lb);
    for (int l = 0; l < 4; l++) {
        k_fwd_w_imm<<<1024, 256, 68608>>>();
        k_fwd_h<<<1024, 272>>>();
        k_spec<<<512, 256>>>(l);
        k_inv_h<<<1024, 256>>>();
        k_fuse<<<4096, 256, 94976>>>(skw, skb, bng, bnb, bnm, bnv, l);
    }
    k_proj<<<2048, 256>>>(pw, pb);
    k_head<<<16, 128>>>(env, d1d, dw1, db1, dw2, db2, dw3, db3,
                        iw1, ib1, iw2, ib2, iw3, ib3, out);
}

// round 16
// speedup vs baseline: 1.0272x; 1.0272x over previous
#include <cuda_runtime.h>
#include <math.h>

#define Bn 16
#define Cn 64
#define Hn 256
#define HWn 65536

__device__ float g_x[Bn*Cn*HWn];       // activations [b][c][h][w] (in place)
__device__ float g_G[Bn*Cn*Hn*32];     // fwd w-DFT: [bc*256+h][kx](re,im)
__device__ float g_F[512*2048];        // fwd spectrum, mode-major: [mode][re|im][bc]
__device__ float g_F2[Bn*Cn*1024];     // after spectral mix [bo][mode][2]
__device__ float g_Gi[Bn*Cn*8192];     // inv h-DFT [bo][kx][h](re,im) interleaved
__device__ float g_part[Bn*Cn*128];    // proj partial sums per (b,o,hb)
__device__ float g_ct[256];
__device__ float g_st[256];
__device__ float2 g_cc2[256];
__device__ float2 g_ss2[256];
__device__ float g_Wtr[4*512*4096];    // transposed weights: [l][mode][i*64+o]
__device__ float g_Wti[4*512*4096];

__device__ __forceinline__ float gelu(float x) {
    return 0.5f * x * (1.0f + erff(x * 0.70710678f));
}

__device__ __forceinline__ float2 ffma2(float2 a, float2 b, float2 c) {
    float2 d;
    asm("fma.rn.f32x2 %0, %1, %2, %3;"
        : "=l"(*(unsigned long long*)&d)
        : "l"(*(unsigned long long*)&a),
          "l"(*(unsigned long long*)&b),
          "l"(*(unsigned long long*)&c));
    return d;
}

// ---------------- compile-time twiddles (forced constant-fold) ----------------
constexpr double TPI_ = 3.141592653589793238462643383279502884;
constexpr double tcos_(double x) {
    double t = 1.0, s = 1.0;
    for (int i = 1; i <= 16; i++) { t = -t * x * x / ((2.0 * i - 1.0) * (2.0 * i)); s += t; }
    return s;
}
constexpr double tsin_(double x) {
    double t = x, s = x;
    for (int i = 1; i <= 16; i++) { t = -t * x * x / ((2.0 * i) * (2.0 * i + 1.0)); s += t; }
    return s;
}
constexpr double ang_(int n) { return ((n <= 128) ? n : n - 256) * (TPI_ / 128.0); }
template<int N> struct TwN {
    static constexpr float C = (float)tcos_(ang_(N));      // cos(2pi N/256)
    static constexpr float S = (float)(-tsin_(ang_(N)));   // -sin(2pi N/256)
};

// unfolded: acc[k] += x * e^{-2pi i (W*k)/256}
template<int W, int K> struct KL {
    static __device__ __forceinline__ void run(float x, float2* a) {
        constexpr int N = (W * K) & 255;
        a[K].x = fmaf(x, TwN<N>::C, a[K].x);
        a[K].y = fmaf(x, TwN<N>::S, a[K].y);
        KL<W, K + 1>::run(x, a);
    }
};
template<int W> struct KL<W, 16> {
    static __device__ __forceinline__ void run(float, float2*) {}
};
// folded pair (w, 256-w): Re += u*cos, Im += v*(-sin)
template<int W, int K> struct KLF {
    static __device__ __forceinline__ void run(float u, float v, float2* a) {
        constexpr int N = (W * K) & 255;
        a[K].x = fmaf(u, TwN<N>::C, a[K].x);
        a[K].y = fmaf(v, TwN<N>::S, a[K].y);
        KLF<W, K + 1>::run(u, v, a);
    }
};
template<int W> struct KLF<W, 16> {
    static __device__ __forceinline__ void run(float, float, float2*) {}
};
template<int C, int J> struct JF {
    static __device__ __forceinline__ void run(const float* xr, float2* a) {
        float lo = xr[J];
        float hi = xr[34 + 32 - J];
        KLF<32 * C + J, 0>::run(lo + hi, lo - hi, a);
        JF<C, J + 1>::run(xr, a);
    }
};
template<int C> struct JF<C, 32> {
    static __device__ __forceinline__ void run(const float*, float2*) {}
};

template<int CC>
__device__ __forceinline__ void fw_pair(int tid, int r0, float* xs, float2* acc) {
    __syncthreads();
    #pragma unroll 2
    for (int i = tid; i < 2048; i += 256) {
        int r = i >> 3, jq = (i & 7) * 4;
        float4 v = *(const float4*)&g_x[(r0 + r) * 256 + CC * 32 + jq];
        float4 w = *(const float4*)&g_x[(r0 + r) * 256 + (7 - CC) * 32 + jq];
        float* p = xs + r * 67 + jq;
        p[0] = v.x; p[1] = v.y; p[2] = v.z; p[3] = v.w;
        float* q = p + 34;
        q[0] = w.x; q[1] = w.y; q[2] = w.z; q[3] = w.w;
    }
    __syncthreads();
    const float* xr = xs + tid * 67;
    KL<CC * 32, 0>::run(xr[0], acc);
    KL<(7 - CC) * 32, 0>::run(xr[34], acc);
    JF<CC, 1>::run(xr, acc);
}

// ---------------- fwd w-DFT (R10 structure, stride 67, measured neutral) ----------------
__global__ void __launch_bounds__(256) k_fwd_w_imm() {
    extern __shared__ float xs[];              // 256*67 floats
    int tid = threadIdx.x, r0 = blockIdx.x * 256;
    float2 acc[16];
    #pragma unroll
    for (int k = 0; k < 16; k++) acc[k] = make_float2(0.f, 0.f);
    fw_pair<0>(tid, r0, xs, acc);
    fw_pair<1>(tid, r0, xs, acc);
    fw_pair<2>(tid, r0, xs, acc);
    fw_pair<3>(tid, r0, xs, acc);
    float* gp = g_G + (r0 + tid) * 32;
    #pragma unroll
    for (int k = 0; k < 8; k++) {
        float4 v = make_float4(acc[2 * k].x, acc[2 * k].y, acc[2 * k + 1].x, acc[2 * k + 1].y);
        *(float4*)&gp[4 * k] = v;
    }
}

// ---------------- init ----------------
__global__ void k_init() {
    int tid = threadIdx.x;
    double s, c;
    sincospi((double)tid / 128.0, &s, &c);
    g_ct[tid] = (float)c;  g_st[tid] = (float)s;
    g_cc2[tid] = make_float2((float)c, (float)c);
    g_ss2[tid] = make_float2((float)s, (float)s);
}

// ---------------- one-time weight transpose ----------------
__global__ void __launch_bounds__(256) k_wprep(const float* __restrict__ w1r, const float* __restrict__ w1i,
                                               const float* __restrict__ w2r, const float* __restrict__ w2i) {
    __shared__ float tile[32][257];
    int bx = blockIdx.x;
    int l = bx & 3, src = (bx >> 2) & 3, io0 = (bx >> 4) * 32;
    const float* sp;
    if      (src == 0) sp = w1r;
    else if (src == 1) sp = w1i;
    else if (src == 2) sp = w2r;
    else               sp = w2i;
    sp += (long)l * 1048576 + (long)io0 * 256;
    int t = threadIdx.x;
    #pragma unroll 4
    for (int io = 0; io < 32; io++) tile[io][t] = sp[io * 256 + t];
    __syncthreads();
    float* tp = ((src & 1) ? g_Wti : g_Wtr) + (long)l * 2097152 + ((src >= 2) ? (long)256 * 4096 : 0) + io0;
    int lane = t & 31, row = t >> 5;
    #pragma unroll 4
    for (int j = 0; j < 32; j++) {
        int m = row + j * 8;
        tp[(long)m * 4096 + lane] = tile[lane][m];
    }
}

// ---------------- lift: o-pair packed ----------------
__global__ void __launch_bounds__(256) k_lift(const float* __restrict__ grid,
                                              const float* __restrict__ lw,
                                              const float* __restrict__ lb) {
    __shared__ float2 wt[480];   // [c][op]
    __shared__ float2 bs2[32];
    int tid = threadIdx.x;
    for (int i = tid; i < 480; i += 256) {
        int c = i >> 5, op = i & 31;
        wt[i] = make_float2(lw[(op * 2) * 15 + c], lw[(op * 2 + 1) * 15 + c]);
    }
    if (tid < 32) bs2[tid] = make_float2(lb[2 * tid], lb[2 * tid + 1]);
    __syncthreads();
    int p = blockIdx.x * 256 + tid;
    int b = p >> 16, hw = p & 65535;
    float2 xx[15];
    const float* gp = grid + b * 15 * HWn + hw;
    #pragma unroll
    for (int c = 0; c < 15; c++) { float x = gp[c * HWn]; xx[c] = make_float2(x, x); }
    float* xp = g_x + b * Cn * HWn + hw;
    #pragma unroll 2
    for (int op = 0; op < 32; op++) {
        float2 a = bs2[op];
        #pragma unroll
        for (int c = 0; c < 15; c++) a = ffma2(xx[c], wt[c * 32 + op], a);
        xp[(2 * op) * HWn]     = gelu(a.x);
        xp[(2 * op + 1) * HWn] = gelu(a.y);
    }
}

// ---------------- fwd h-DFT: conjugate-pair folded (R10) ----------------
__global__ void __launch_bounds__(272) k_fwd_h() {
    __shared__ float Gs[8192];
    __shared__ float2 scc[256], sss[256];
    int tid = threadIdx.x, bc = blockIdx.x;
    const float* gp = g_G + bc * 8192;
    for (int i = tid; i < 8192; i += 272) Gs[i] = gp[i];
    for (int i = tid; i < 256; i += 272) { scc[i] = g_cc2[i]; sss[i] = g_ss2[i]; }
    __syncthreads();
    int sp = tid >> 4, kx = tid & 15;
    int kyv = (sp == 16) ? 240 : sp;
    float2 P = make_float2(0.f, 0.f), Q = make_float2(0.f, 0.f);
    int idx = 0;
    #pragma unroll 4
    for (int h = 0; h < 256; h++) {
        float2 g = *(const float2*)&Gs[h * 32 + kx * 2];
        P = ffma2(g, scc[idx], P);
        Q = ffma2(g, sss[idx], Q);
        idx = (idx + kyv) & 255;
    }
    int m = sp * 16 + kx;
    g_F[m * 2048 + bc]        = P.x + Q.y;
    g_F[m * 2048 + 1024 + bc] = P.y - Q.x;
    if (sp >= 1 && sp <= 15) {
        int m2 = (32 - sp) * 16 + kx;
        g_F[m2 * 2048 + bc]        = P.x - Q.y;
        g_F[m2 * 2048 + 1024 + bc] = P.y + Q.x;
    }
}

// ---------------- spectral multiply (R8) ----------------
__global__ void __launch_bounds__(256) k_spec(int l) {
    __shared__ float Wr[4096], Wi[4096], Ar[1024], Ai[1024];
    int m = blockIdx.x, t = threadIdx.x;
    const float* wr = g_Wtr + (long)l * 2097152 + (long)m * 4096;
    const float* wi = g_Wti + (long)l * 2097152 + (long)m * 4096;
    for (int i = t; i < 4096; i += 256) { Wr[i] = wr[i]; Wi[i] = wi[i]; }
    const float* fp = g_F + (long)m * 2048;
    for (int i = t; i < 1024; i += 256) { Ar[i] = fp[i]; Ai[i] = fp[1024 + i]; }
    __syncthreads();
    int o = t & 63, bq = t >> 6;
    float orr[4], oii[4];
    #pragma unroll
    for (int u = 0; u < 4; u++) { orr[u] = 0.f; oii[u] = 0.f; }
    for (int i = 0; i < 64; i++) {
        float wrv = Wr[i * 64 + o], wiv = Wi[i * 64 + o];
        #pragma unroll
        for (int u = 0; u < 4; u++) {
            float arv = Ar[(bq * 4 + u) * 64 + i], aiv = Ai[(bq * 4 + u) * 64 + i];
            orr[u] = fmaf(arv, wrv, fmaf(-aiv, wiv, orr[u]));
            oii[u] = fmaf(arv, wiv, fmaf( aiv, wrv, oii[u]));
        }
    }
    #pragma unroll
    for (int u = 0; u < 4; u++) {
        int b = bq * 4 + u;
        *(float2*)&g_F2[(b * 64 + o) * 1024 + m * 2] = make_float2(orr[u], oii[u]);
    }
}

// ---------------- inv h-DFT (R8) ----------------
__global__ void __launch_bounds__(256) k_inv_h() {
    __shared__ float Fs[1024];
    __shared__ float2 scc[256], sss[256];
    int tid = threadIdx.x, bo = blockIdx.x;
    const float* fp = g_F2 + bo * 1024;
    for (int i = tid; i < 1024; i += 256) Fs[i] = fp[i];
    scc[tid] = g_cc2[tid]; sss[tid] = g_ss2[tid];
    __syncthreads();
    int h = tid;
    float2 P[16], Q[16];
    #pragma unroll
    for (int k = 0; k < 16; k++) { P[k] = make_float2(0.f, 0.f); Q[k] = make_float2(0.f, 0.f); }
    #pragma unroll 2
    for (int s = 0; s < 32; s++) {
        int ky = (s < 16) ? s : s + 224;
        int idx = (ky * h) & 255;
        float2 cc = scc[idx], ss = sss[idx];
        #pragma unroll
        for (int q = 0; q < 8; q++) {
            float4 f4 = *(const float4*)&Fs[s * 32 + q * 4];
            float2 fa = make_float2(f4.x, f4.y), fb = make_float2(f4.z, f4.w);
            P[2 * q]     = ffma2(fa, cc, P[2 * q]);     Q[2 * q]     = ffma2(fa, ss, Q[2 * q]);
            P[2 * q + 1] = ffma2(fb, cc, P[2 * q + 1]); Q[2 * q + 1] = ffma2(fb, ss, Q[2 * q + 1]);
        }
    }
    float2* go = (float2*)g_Gi + bo * 4096 + h;
    #pragma unroll
    for (int k = 0; k < 16; k++) {
        float sc = (k == 0 ? 1.f : 2.f) * (1.f / 65536.f);
        go[k * 256] = make_float2((P[k].x - Q[k].y) * sc, (P[k].y + Q[k].x) * sc);
    }
}

// ---------------- fused inv w-DFT + skip conv + BN + gelu + residual (R12 fills; float4 epilogue) ----------------
__global__ void __launch_bounds__(256, 2) k_fuse(const float* __restrict__ skw, const float* __restrict__ skb,
                                                 const float* __restrict__ bng, const float* __restrict__ bnb,
                                                 const float* __restrict__ bnm, const float* __restrict__ bnv,
                                                 int l) {
    extern __shared__ float sm[];
    float* xs   = sm;              // 16896 = 64*264
    float* swt  = xs + 16896;      // 4096: [c][o]
    float* gis  = swt + 4096;      // 2048: [kx][ri][o], ri=1 negated
    float* ctb  = gis + 2048;      // 256
    float* stb  = ctb + 256;       // 256
    float* bnA  = stb + 256;       // 64
    float* bnB  = bnA + 64;        // 64
    float* sbbv = bnB + 64;        // 64
    int tid = threadIdx.x;
    int b = blockIdx.x >> 8, h = blockIdx.x & 255;
    float* xp = g_x + b * 64 * HWn + h * 256;
    for (int c = 0; c < 64; c++) xs[c * 264 + tid] = xp[c * HWn + tid];
    for (int i = tid; i < 4096; i += 256) {
        int o = i >> 6, c = i & 63;
        swt[c * 64 + o] = skw[l * 4096 + i];
    }
    for (int i = tid; i < 1024; i += 256) {
        int o = i >> 4, kx = i & 15;
        float2 v = ((const float2*)g_Gi)[(b * 64 + o) * 4096 + kx * 256 + h];
        gis[(kx * 2) * 64 + o]     = v.x;
        gis[(kx * 2 + 1) * 64 + o] = -v.y;
    }
    ctb[tid] = g_ct[tid];  stb[tid] = g_st[tid];
    if (tid < 64) {
        float A = bng[l * 64 + tid] * rsqrtf(bnv[l * 64 + tid] + 1e-5f);
        bnA[tid] = A;
        bnB[tid] = fmaf(-bnm[l * 64 + tid], A, bnb[l * 64 + tid]);
        sbbv[tid] = skb[l * 64 + tid];
    }
    __syncthreads();
    int wb = (tid & 63) * 4, ob = (tid >> 6) * 16;
    float2 acc[8][4];
    #pragma unroll
    for (int ip = 0; ip < 8; ip++) {
        float2 bias = *(const float2*)&sbbv[ob + ip * 2];
        acc[ip][0] = bias; acc[ip][1] = bias; acc[ip][2] = bias; acc[ip][3] = bias;
    }
    for (int c = 0; c < 64; c++) {
        float4 xv = *(const float4*)&xs[c * 264 + wb];
        float2 x0 = make_float2(xv.x, xv.x), x1 = make_float2(xv.y, xv.y);
        float2 x2 = make_float2(xv.z, xv.z), x3 = make_float2(xv.w, xv.w);
        #pragma unroll
        for (int ip = 0; ip < 8; ip++) {
            float2 wv = *(const float2*)&swt[c * 64 + ob + ip * 2];
            acc[ip][0] = ffma2(x0, wv, acc[ip][0]);
            acc[ip][1] = ffma2(x1, wv, acc[ip][1]);
            acc[ip][2] = ffma2(x2, wv, acc[ip][2]);
            acc[ip][3] = ffma2(x3, wv, acc[ip][3]);
        }
    }
    float dc[4], ds[4], tc_[4], ts_[4];
    #pragma unroll
    for (int j = 0; j < 4; j++) {
        dc[j] = ctb[wb + j];  ds[j] = stb[wb + j];
        tc_[j] = 1.f;  ts_[j] = 0.f;
    }
    #pragma unroll 4
    for (int kx = 0; kx < 16; kx++) {
        float2 cc0 = make_float2(tc_[0], tc_[0]), ss0 = make_float2(ts_[0], ts_[0]);
        float2 cc1 = make_float2(tc_[1], tc_[1]), ss1 = make_float2(ts_[1], ts_[1]);
        float2 cc2 = make_float2(tc_[2], tc_[2]), ss2 = make_float2(ts_[2], ts_[2]);
        float2 cc3 = make_float2(tc_[3], tc_[3]), ss3 = make_float2(ts_[3], ts_[3]);
        #pragma unroll
        for (int ip = 0; ip < 8; ip++) {
            float2 gr = *(const float2*)&gis[(kx * 2) * 64 + ob + ip * 2];
            float2 gi = *(const float2*)&gis[(kx * 2 + 1) * 64 + ob + ip * 2];
            acc[ip][0] = ffma2(gr, cc0, acc[ip][0]);  acc[ip][0] = ffma2(gi, ss0, acc[ip][0]);
            acc[ip][1] = ffma2(gr, cc1, acc[ip][1]);  acc[ip][1] = ffma2(gi, ss1, acc[ip][1]);
            acc[ip][2] = ffma2(gr, cc2, acc[ip][2]);  acc[ip][2] = ffma2(gi, ss2, acc[ip][2]);
            acc[ip][3] = ffma2(gr, cc3, acc[ip][3]);  acc[ip][3] = ffma2(gi, ss3, acc[ip][3]);
        }
        #pragma unroll
        for (int j = 0; j < 4; j++) {
            float nc = tc_[j] * dc[j] - ts_[j] * ds[j];
            ts_[j] = fmaf(tc_[j], ds[j], ts_[j] * dc[j]);
            tc_[j] = nc;
        }
    }
    #pragma unroll
    for (int ip = 0; ip < 8; ip++) {
        int o0 = ob + ip * 2, o1 = o0 + 1;
        float A0 = bnA[o0], B0 = bnB[o0], A1 = bnA[o1], B1 = bnB[o1];
        float4 res0 = *(const float4*)&xs[o0 * 264 + wb];
        float4 res1 = *(const float4*)&xs[o1 * 264 + wb];
        float4 r0, r1;
        r0.x = gelu(fmaf(acc[ip][0].x, A0, B0)) + res0.x;
        r0.y = gelu(fmaf(acc[ip][1].x, A0, B0)) + res0.y;
        r0.z = gelu(fmaf(acc[ip][2].x, A0, B0)) + res0.z;
        r0.w = gelu(fmaf(acc[ip][3].x, A0, B0)) + res0.w;
        r1.x = gelu(fmaf(acc[ip][0].y, A1, B1)) + res1.x;
        r1.y = gelu(fmaf(acc[ip][1].y, A1, B1)) + res1.y;
        r1.z = gelu(fmaf(acc[ip][2].y, A1, B1)) + res1.z;
        r1.w = gelu(fmaf(acc[ip][3].y, A1, B1)) + res1.w;
        *(float4*)&xp[o0 * HWn + wb] = r0;
        *(float4*)&xp[o1 * HWn + wb] = r1;
    }
}

// ---------------- proj conv + gelu + partial mean: 2 pixels/thread, o-pair packed ----------------
__global__ void __launch_bounds__(256) k_proj(const float* __restrict__ pw, const float* __restrict__ pb) {
    __shared__ float2 pwt[2048];    // [c][op]
    __shared__ float2 pbs[32];
    __shared__ float wsum[64][8];
    int tid = threadIdx.x;
    int b = blockIdx.x >> 7, hb = blockIdx.x & 127;
    for (int i = tid; i < 2048; i += 256) {
        int c = i >> 5, op = i & 31;
        pwt[i] = make_float2(pw[(op * 2) * 64 + c], pw[(op * 2 + 1) * 64 + c]);
    }
    if (tid < 32) pbs[tid] = make_float2(pb[2 * tid], pb[2 * tid + 1]);
    __syncthreads();
    const float* xp = g_x + (b * 64) * HWn + hb * 512 + tid;
    float xv0[64], xv1[64];
    #pragma unroll
    for (int c = 0; c < 64; c++) { xv0[c] = xp[c * HWn]; xv1[c] = xp[c * HWn + 256]; }
    int lane = tid & 31, wid = tid >> 5;
    #pragma unroll 1
    for (int g = 0; g < 8; g++) {
        float2 a0[4], a1[4];
        #pragma unroll
        for (int j = 0; j < 4; j++) { float2 bi = pbs[g * 4 + j]; a0[j] = bi; a1[j] = bi; }
        #pragma unroll
        for (int c = 0; c < 64; c++) {
            float2 x0 = make_float2(xv0[c], xv0[c]);
            float2 x1 = make_float2(xv1[c], xv1[c]);
            #pragma unroll
            for (int j = 0; j < 4; j++) {
                float2 wv = pwt[c * 32 + g * 4 + j];
                a0[j] = ffma2(x0, wv, a0[j]);
                a1[j] = ffma2(x1, wv, a1[j]);
            }
        }
        #pragma unroll
        for (int j = 0; j < 4; j++) {
            float v0 = gelu(a0[j].x) + gelu(a1[j].x);
            float v1 = gelu(a0[j].y) + gelu(a1[j].y);
            #pragma unroll
            for (int off = 16; off; off >>= 1) {
                v0 += __shfl_down_sync(0xffffffffu, v0, off);
                v1 += __shfl_down_sync(0xffffffffu, v1, off);
            }
            if (lane == 0) {
                wsum[g * 8 + j * 2][wid]     = v0;
                wsum[g * 8 + j * 2 + 1][wid] = v1;
            }
        }
    }
    __syncthreads();
    if (tid < 64) {
        float s = 0.f;
        #pragma unroll
        for (int j = 0; j < 8; j++) s += wsum[tid][j];
        g_part[(b * 64 + tid) * 128 + hb] = s;
    }
}

__global__ void __launch_bounds__(128) k_head(const float* __restrict__ env, const float* __restrict__ d1d,
    const float* __restrict__ dw1, const float* __restrict__ db1,
    const float* __restrict__ dw2, const float* __restrict__ db2,
    const float* __restrict__ dw3, const float* __restrict__ db3,
    const float* __restrict__ iw1, const float* __restrict__ ib1,
    const float* __restrict__ iw2, const float* __restrict__ ib2,
    const float* __restrict__ iw3, const float* __restrict__ ib3,
    float* __restrict__ out) {
    __shared__ float feat[108], h1[128], h2[64];
    int b = blockIdx.x, t = threadIdx.x;
    if (t < 64) {
        float s = 0.f;
        const float* pp = g_part + (b * 64 + t) * 128;
        for (int h = 0; h < 128; h++) s += pp[h];
        feat[t] = s * (1.0f / 65536.0f);
    } else if (t < 104) feat[t] = env[b * 40 + t - 64];
    else if (t < 108)   feat[t] = d1d[b * 4 + t - 104];
    __syncthreads();
    { float a = db1[t];
      for (int k = 0; k < 108; k++) a = fmaf(feat[k], dw1[t * 108 + k], a);
      h1[t] = gelu(a); }
    __syncthreads();
    if (t < 64) { float a = db2[t];
      for (int k = 0; k < 128; k++) a = fmaf(h1[k], dw2[t * 128 + k], a);
      h2[t] = gelu(a); }
    __syncthreads();
    if (t < 8) { float a = db3[t];
      for (int k = 0; k < 64; k++) a = fmaf(h2[k], dw3[t * 64 + k], a);
      out[b * 8 + t] = a; }
    __syncthreads();
    { float a = ib1[t];
      for (int k = 0; k < 108; k++) a = fmaf(feat[k], iw1[t * 108 + k], a);
      h1[t] = gelu(a); }
    __syncthreads();
    if (t < 64) { float a = ib2[t];
      for (int k = 0; k < 128; k++) a = fmaf(h1[k], iw2[t * 128 + k], a);
      h2[t] = gelu(a); }
    __syncthreads();
    if (t < 4) { float a = ib3[t];
      for (int k = 0; k < 64; k++) a = fmaf(h2[k], iw3[t * 64 + k], a);
      out[128 + b * 4 + t] = a; }
}

extern "C" void kernel_launch(void* const* d_in, const int* in_sizes, int n_in,
                              void* d_out, int out_size) {
    const float* grid_in = (const float*)d_in[0];
    const float* env  = (const float*)d_in[1];
    const float* d1d  = (const float*)d_in[2];
    const float* lw   = (const float*)d_in[3];
    const float* lb   = (const float*)d_in[4];
    const float* w1r  = (const float*)d_in[5];
    const float* w1i  = (const float*)d_in[6];
    const float* w2r  = (const float*)d_in[7];
    const float* w2i  = (const float*)d_in[8];
    const float* skw  = (const float*)d_in[9];
    const float* skb  = (const float*)d_in[10];
    const float* bng  = (const float*)d_in[11];
    const float* bnb  = (const float*)d_in[12];
    const float* bnm  = (const float*)d_in[13];
    const float* bnv  = (const float*)d_in[14];
    const float* pw   = (const float*)d_in[15];
    const float* pb   = (const float*)d_in[16];
    const float* dw1  = (const float*)d_in[17];
    const float* db1  = (const float*)d_in[18];
    const float* dw2  = (const float*)d_in[19];
    const float* db2  = (const float*)d_in[20];
    const float* dw3  = (const float*)d_in[21];
    const float* db3  = (const float*)d_in[22];
    const float* iw1  = (const float*)d_in[23];
    const float* ib1  = (const float*)d_in[24];
    const float* iw2  = (const float*)d_in[25];
    const float* ib2  = (const float*)d_in[26];
    const float* iw3  = (const float*)d_in[27];
    const float* ib3  = (const float*)d_in[28];
    float* out = (float*)d_out;

    static bool attr_done = false;
    if (!attr_done) {
        cudaFuncSetAttribute(k_fwd_w_imm, cudaFuncAttributeMaxDynamicSharedMemorySize, 68608);
        cudaFuncSetAttribute(k_fuse, cudaFuncAttributeMaxDynamicSharedMemorySize, 94976);
        attr_done = true;
    }

    k_init<<<1, 256>>>();
    k_wprep<<<2048, 256>>>(w1r, w1i, w2r, w2i);
    k_lift<<<4096, 256>>>(grid_in, lw, lb);
    for (int l = 0; l < 4; l++) {
        k_fwd_w_imm<<<1024, 256, 68608>>>();
        k_fwd_h<<<1024, 272>>>();
        k_spec<<<512, 256>>>(l);
        k_inv_h<<<1024, 256>>>();
        k_fuse<<<4096, 256, 94976>>>(skw, skb, bng, bnb, bnm, bnv, l);
    }
    k_proj<<<2048, 256>>>(pw, pb);
    k_head<<<16, 128>>>(env, d1d, dw1, db1, dw2, db2, dw3, db3,
                        iw1, ib1, iw2, ib2, iw3, ib3, out);
}